// round 12
// baseline (speedup 1.0000x reference)
#include <cuda_runtime.h>
#include <cuda_fp16.h>
#include <math.h>
#include <cstdint>

#define B_    32
#define N_    32
#define E_    128
#define CIN_  64
#define COUT_ 128
#define H_    128
#define W_    128

// ---------------------------------------------------------------------------
// Device scratch
// ---------------------------------------------------------------------------
__device__ float g_out_node_t[B_ * COUT_ * N_];      // [b][o][n]
__device__ __half g_state_f16[B_ * H_ * W_ * CIN_];  // BHWC fp16
__device__ __half g_wt_f16[9 * COUT_ * CIN_];        // [kk][cout][cin] fp16
__device__ float g_Qn[N_ * E_];                      // node @ wQ_top (written
__device__ float g_Kn[N_ * E_];                      //  redundantly by all 32
__device__ float g_Vn[N_ * E_];                      //  attn blocks, same bits)

// ---------------------------------------------------------------------------
// Helpers
// ---------------------------------------------------------------------------
__device__ __forceinline__ uint32_t smem_u32(const void* p) {
    uint32_t a;
    asm("{ .reg .u64 t; cvta.to.shared.u64 t, %1; cvt.u32.u64 %0, t; }" : "=r"(a) : "l"(p));
    return a;
}
#define SWZ(o) ((o) ^ (((o) >> 3) & 0x70))

__device__ __forceinline__ void cp_async16(uint32_t dst, const void* src, uint32_t srcsize) {
    asm volatile("cp.async.cg.shared.global [%0], [%1], 16, %2;"
                 :: "r"(dst), "l"(src), "r"(srcsize) : "memory");
}
#define CP_COMMIT() asm volatile("cp.async.commit_group;" ::: "memory")

__device__ __forceinline__ void ldm_x4(uint32_t* r, uint32_t addr) {
    asm volatile("ldmatrix.sync.aligned.m8n8.x4.shared.b16 {%0,%1,%2,%3}, [%4];"
                 : "=r"(r[0]), "=r"(r[1]), "=r"(r[2]), "=r"(r[3]) : "r"(addr));
}
__device__ __forceinline__ void mma_fp16(float* c, const uint32_t* a,
                                         uint32_t b0, uint32_t b1) {
    asm volatile(
        "mma.sync.aligned.m16n8k16.row.col.f32.f16.f16.f32 "
        "{%0,%1,%2,%3}, {%4,%5,%6,%7}, {%8,%9}, {%0,%1,%2,%3};"
        : "+f"(c[0]), "+f"(c[1]), "+f"(c[2]), "+f"(c[3])
        : "r"(a[0]), "r"(a[1]), "r"(a[2]), "r"(a[3]), "r"(b0), "r"(b1));
}
__device__ __forceinline__ float dot4(float4 a, float4 b) {
    return a.x * b.x + a.y * b.y + a.z * b.z + a.w * b.w;
}

// ---------------------------------------------------------------------------
// Kernel 1 (mega-aux): state-convert ∪ w-convert ∪ self-contained attention.
//   blocks [0, 4096)      : state fp32 NCHW -> fp16 BHWC, 64c x 128w tiles
//   blocks [4096, 4384)   : conv weights -> [kk][cout][cin] fp16
//   blocks [4384, 4416)   : full attention for batch b (computes own QKV)
// ---------------------------------------------------------------------------
#define AUX_STATE_BLKS 4096
#define AUX_W_BLKS     288
#define AUX_TOTAL_BLKS (AUX_STATE_BLKS + AUX_W_BLKS + 32)

// shared union: state branch uses 32KB (64x32 float4), attn branch ~24KB
__global__ void __launch_bounds__(256)
aux_kernel(const float* __restrict__ state,
           const float* __restrict__ conv_w,
           const float* __restrict__ node_embeds,
           const float* __restrict__ goal_embed,
           const float* __restrict__ wQ,
           const float* __restrict__ wK,
           const float* __restrict__ wV,
           const float* __restrict__ final_w,
           const float* __restrict__ final_b) {
    __shared__ __align__(16) char smem_u[33024];
    const int bx  = blockIdx.x;
    const int tid = threadIdx.x;

    if (bx < AUX_STATE_BLKS) {
        // ================= state convert: bx = hh + 128*b =================
        const int hh = bx & 127;
        const int b  = bx >> 7;
        float4* sf4 = (float4*)smem_u;            // [64][32] chunk-swizzled
        float*  sf  = (float*)smem_u;

        // Phase A: float4 loads (coalesced 512B/warp), swizzled STS.128
#pragma unroll
        for (int p = 0; p < 8; p++) {
            int i  = tid + p * 256;               // 0..2047
            int c  = i >> 5;
            int w4 = i & 31;
            float4 v = *(const float4*)(state +
                (((size_t)(b * 64 + c) * 128 + hh) * 128) + 4 * w4);
            sf4[c * 32 + (w4 ^ (c >> 3))] = v;
        }
        __syncthreads();

        // Phase B: conflict-free gather of 8 channels per (w), uint4 STG
        const int ck = tid & 7;
#pragma unroll
        for (int q = 0; q < 4; q++) {
            int w = 32 * q + (tid >> 3);
            union { __half h[8]; uint4 u; } ph;
#pragma unroll
            for (int j = 0; j < 8; j++) {
                int c = ck * 8 + j;               // c>>3 == ck
                float x = sf[c * 128 + (((w >> 2) ^ ck) << 2) + (w & 3)];
                ph.h[j] = __float2half_rn(x);
            }
            *(uint4*)(g_state_f16 +
                (((size_t)(b * 128 + hh) * 128) + w) * 64 + ck * 8) = ph.u;
        }
    } else if (bx < AUX_STATE_BLKS + AUX_W_BLKS) {
        // ================= weight transpose/convert =================
        int i = (bx - AUX_STATE_BLKS) * 256 + tid;
        int kk = i >> 13;
        int r  = i & 8191;
        int o  = r >> 6;
        int c  = r & 63;
        g_wt_f16[i] = __float2half_rn(conv_w[(o * 64 + c) * 9 + kk]);
    } else {
        // ================= self-contained attention, one block per batch ====
        float* U    = (float*)smem_u;
        float* vnf_s = U;              // [128][33] later; first 4096 = node_s
        float* node_s = U;             // [32][128] during QKV phase
        float* sg   = U + 4224;
        float* sqg  = U + 4352;
        float* skg  = U + 4480;
        float* svg  = U + 4608;
        float* su   = U + 4736;
        float* sv   = U + 4768;
        float* ss0  = U + 4800;
        float* svgf = U + 4832;        // 128
        float* sP   = U + 4960;        // 32*32

        const int b = bx - AUX_STATE_BLKS - AUX_W_BLKS;

        // Phase 0: stage node embeds + goal
        for (int i = tid; i < 4096; i += 256) node_s[i] = node_embeds[i];
        if (tid < 128) sg[tid] = goal_embed[b * 128 + tid];
        __syncthreads();

        // Phase 1: QKV (batch-independent halves) -> globals (benign
        // redundant identical writes across blocks)
        {
            const int k  = tid & 127;
            const int ng = tid >> 7;       // 0/1 -> n 0-15 / 16-31
#pragma unroll
            for (int m = 0; m < 3; m++) {
                const float* wm = (m == 0) ? wQ : (m == 1) ? wK : wV;
                float* gout = (m == 0) ? g_Qn : (m == 1) ? g_Kn : g_Vn;
                float acc[16];
#pragma unroll
                for (int n = 0; n < 16; n++) acc[n] = 0.f;
                for (int f = 0; f < 128; f++) {
                    float wv = __ldg(&wm[f * 128 + k]);
#pragma unroll
                    for (int n = 0; n < 16; n++)
                        acc[n] += node_s[(ng * 16 + n) * 128 + f] * wv;
                }
#pragma unroll
                for (int n = 0; n < 16; n++)
                    gout[(ng * 16 + n) * 128 + k] = acc[n];
            }
        }
        __threadfence_block();
        __syncthreads();

        // Phase 2: qg / kg (256 threads), then vg (128 threads)
        {
            int k = tid & 127;
            const float* w = (tid >> 7) ? wK : wQ;
            float acc = 0.f;
#pragma unroll 4
            for (int f = 0; f < 128; f++) acc += sg[f] * __ldg(&w[(128 + f) * 128 + k]);
            ((tid >> 7) ? skg : sqg)[k] = acc;
        }
        if (tid < 128) {
            float acc = 0.f;
#pragma unroll 4
            for (int f = 0; f < 128; f++) acc += sg[f] * __ldg(&wV[(128 + f) * 128 + tid]);
            svg[tid] = acc;
        }
        __syncthreads();

        // Phase 3: rank-1 pieces (plain loads for g_Qn/Kn/Vn — same-block data)
        if (tid < 32) {
            const float4* qa = (const float4*)(g_Qn + tid * 128);
            float a = 0.f;
#pragma unroll
            for (int t = 0; t < 32; t++) a += dot4(qa[t], *(float4*)&skg[t * 4]);
            su[tid] = a;
        } else if (tid < 64) {
            const float4* ka = (const float4*)(g_Kn + (tid - 32) * 128);
            float a = 0.f;
#pragma unroll
            for (int t = 0; t < 32; t++) a += dot4(ka[t], *(float4*)&sqg[t * 4]);
            sv[tid - 32] = a;
        } else if (tid == 64) {
            float a = 0.f;
#pragma unroll
            for (int t = 0; t < 32; t++) a += dot4(*(float4*)&sqg[t * 4], *(float4*)&skg[t * 4]);
            ss0[0] = a;
        } else if (tid >= 128) {
            int o = tid - 128;
            const float4* fw = (const float4*)(final_w + o * 128);
            float a = __ldg(&final_b[o]);
#pragma unroll
            for (int t = 0; t < 32; t++) a += dot4(*(float4*)&svg[t * 4], __ldg(&fw[t]));
            svgf[o] = a;
        }
        // Vnf[n][o] into vnf_s (node_s region dead after phase 1 + sync)
        for (int i = tid; i < 4096; i += 256) {
            int n = i >> 7, o = i & 127;
            const float4* va = (const float4*)(g_Vn + n * 128);
            const float4* fw = (const float4*)(final_w + o * 128);
            float a = 0.f;
#pragma unroll
            for (int t = 0; t < 32; t++) a += dot4(va[t], __ldg(&fw[t]));
            vnf_s[o * 33 + n] = a;
        }
        __syncthreads();

        // Phase 4: scores (S0 recomputed locally + rank-1 corrections)
        {
            int q = tid >> 3, n0 = (tid & 7) * 4;
            const float4* qa = (const float4*)(g_Qn + q * 128);
#pragma unroll
            for (int j = 0; j < 4; j++) {
                int n = n0 + j;
                const float4* ka = (const float4*)(g_Kn + n * 128);
                float a = 0.f;
#pragma unroll
                for (int t = 0; t < 32; t++) a += dot4(qa[t], ka[t]);
                sP[q * 32 + n] = (a + su[q] + sv[n] + ss0[0]) * 0.08838834764831845f;
            }
        }
        __syncthreads();

        // Phase 5: softmax rows
        if (tid < 32) {
            const int q = tid;
            float mx = -1e30f;
#pragma unroll
            for (int n = 0; n < 32; n++) mx = fmaxf(mx, sP[q * 32 + n]);
            float s = 0.f;
#pragma unroll
            for (int n = 0; n < 32; n++) {
                float e = expf(sP[q * 32 + n] - mx);
                sP[q * 32 + n] = e;
                s += e;
            }
            float inv = 1.f / s;
#pragma unroll
            for (int n = 0; n < 32; n++) sP[q * 32 + n] *= inv;
        }
        __syncthreads();

        // Phase 6: out_node_t[b][o][q] = P[q] . vnf[:, o] + svgf[o]
        {
            int o = tid >> 1, q0 = (tid & 1) * 16;
            const float* vr = vnf_s + o * 33;
#pragma unroll
            for (int qq = 0; qq < 16; qq++) {
                int q = q0 + qq;
                float a = svgf[o];
#pragma unroll
                for (int n = 0; n < 32; n++) a += sP[q * 32 + n] * vr[n];
                g_out_node_t[b * 4096 + o * 32 + q] = a;
            }
        }
    }
}

// ---------------------------------------------------------------------------
// Kernel 2: conv as fp16 mma.sync GEMM, 2 CTAs/SM, 3-stage B ring.
// CTA = (h, b): M=128 pixels, N=128 couts, K = 9 x 64.
// SMEM: A 48KB + B 3x16KB + zero. 256 threads, warp tile 64x32.
// ---------------------------------------------------------------------------
#define SMEM_B_OFF   49152
#define SMEM_Z_OFF   98304
#define CONV_SMEM    98560
#define NODET_OFF    67584
#define NIDX_OFF     84480

__global__ void __launch_bounds__(256, 2)
conv_mma_kernel(const float* __restrict__ conv_b,
                const int*   __restrict__ board,
                const int*   __restrict__ c2n,
                float*       __restrict__ out) {
    extern __shared__ char smem[];
    const uint32_t sA = smem_u32(smem);
    const int h   = blockIdx.x;
    const int b   = blockIdx.y;
    const int tid = threadIdx.x;
    const int lane = tid & 31;
    const int wid  = tid >> 5;
    const int wm = wid & 1;
    const int wn = wid >> 1;

    if (tid < 16) *(uint4*)(smem + SMEM_Z_OFF + tid * 16) = make_uint4(0, 0, 0, 0);

    // ---- stage A: 3 input rows (h-1..h+1) ----
#pragma unroll
    for (int t = 0; t < 12; t++) {
        int i = tid + t * 256;
        int r = i >> 10;
        int j = i & 1023;
        int w = j >> 3, ck = j & 7;
        int hr = h - 1 + r;
        uint32_t oksz = ((unsigned)hr < 128u) ? 16u : 0u;
        int hrc = hr < 0 ? 0 : (hr > 127 ? 127 : hr);
        const void* src = g_state_f16 + (((size_t)(b * 128 + hrc) * 128) + w) * 64 + ck * 8;
        cp_async16(sA + r * 16384 + SWZ(w * 128 + ck * 16), src, oksz);
    }
    // ---- B tap 0 -> buf0 (group 0, with A) ----
#pragma unroll
    for (int t = 0; t < 4; t++) {
        int i = tid + t * 256;
        int n = i >> 3, ck = i & 7;
        cp_async16(sA + SMEM_B_OFF + SWZ(n * 128 + ck * 16),
                   g_wt_f16 + n * 64 + ck * 8, 16);
    }
    CP_COMMIT();
    // ---- B tap 1 -> buf1 (group 1) ----
#pragma unroll
    for (int t = 0; t < 4; t++) {
        int i = tid + t * 256;
        int n = i >> 3, ck = i & 7;
        cp_async16(sA + SMEM_B_OFF + 16384 + SWZ(n * 128 + ck * 16),
                   g_wt_f16 + 8192 + n * 64 + ck * 8, 16);
    }
    CP_COMMIT();

    float c[64];
#pragma unroll
    for (int j = 0; j < 64; j++) c[j] = 0.f;

    const int lrow = lane & 15;
    const uint32_t khA = (uint32_t)((lane >> 4) << 4);
    const int nrow = (lane & 7) | ((lane & 16) >> 1);
    const uint32_t khB = (uint32_t)(((lane >> 3) & 1) << 4);
    const int wb0 = wm * 64 + lrow;
    const uint32_t zaddr = sA + SMEM_Z_OFF;
    int nbs[2];
#pragma unroll
    for (int nt2 = 0; nt2 < 2; nt2++) nbs[nt2] = wn * 32 + nt2 * 16 + nrow;

#pragma unroll
    for (int kk = 0; kk < 9; kk++) {
        if (kk < 8) asm volatile("cp.async.wait_group 1;" ::: "memory");
        else        asm volatile("cp.async.wait_group 0;" ::: "memory");
        __syncthreads();

        // prefetch tap kk+2 into buf (kk+2)%3
        if (kk <= 6) {
            const __half* src_base = g_wt_f16 + (kk + 2) * 8192;
            const uint32_t dst_base = sA + SMEM_B_OFF + (uint32_t)((kk + 2) % 3) * 16384;
#pragma unroll
            for (int t = 0; t < 4; t++) {
                int i = tid + t * 256;
                int n = i >> 3, ck = i & 7;
                cp_async16(dst_base + SWZ(n * 128 + ck * 16), src_base + n * 64 + ck * 8, 16);
            }
            CP_COMMIT();
        }

        const int dy = kk / 3, dx = kk - dy * 3;
        uint32_t aHi[4], aXr[4];
#pragma unroll
        for (int mt = 0; mt < 4; mt++) {
            int wv = wb0 + mt * 16 + dx - 1;
            bool ok = (unsigned)wv < 128u;
            aHi[mt] = ok ? (sA + (uint32_t)dy * 16384 + (uint32_t)wv * 128) : zaddr;
            aXr[mt] = ok ? (uint32_t)((wv & 7) << 4) : 0u;
        }
        const uint32_t bB = sA + SMEM_B_OFF + (uint32_t)(kk % 3) * 16384;
        uint32_t bHi[2], bXr[2];
#pragma unroll
        for (int nt2 = 0; nt2 < 2; nt2++) {
            bHi[nt2] = bB + (uint32_t)nbs[nt2] * 128;
            bXr[nt2] = (uint32_t)((nbs[nt2] & 7) << 4);
        }

#pragma unroll
        for (int ks = 0; ks < 4; ks++) {
            const uint32_t kA = (uint32_t)(ks * 32) + khA;
            const uint32_t kB = (uint32_t)(ks * 32) + khB;
            uint32_t bh[8];
            ldm_x4(bh,     bHi[0] + (kB ^ bXr[0]));
            ldm_x4(bh + 4, bHi[1] + (kB ^ bXr[1]));
            uint32_t ah[16];
#pragma unroll
            for (int mt = 0; mt < 4; mt++)
                ldm_x4(ah + 4 * mt, aHi[mt] + (kA ^ aXr[mt]));
#pragma unroll
            for (int mt = 0; mt < 4; mt++)
#pragma unroll
                for (int nt = 0; nt < 4; nt++) {
                    int bi = (nt >> 1) * 4 + (nt & 1) * 2;
                    mma_fp16(c + (mt * 4 + nt) * 4, ah + 4 * mt, bh[bi], bh[bi + 1]);
                }
        }
    }
    __syncthreads();

    // ---- epilogue ----
    float* acc_s  = (float*)smem;                 // 128 x 132
    float* node_t = (float*)(smem + NODET_OFF);   // [o][n] pad 33
    int*   nidx_s = (int*)(smem + NIDX_OFF);

#pragma unroll
    for (int mt = 0; mt < 4; mt++)
#pragma unroll
        for (int nt = 0; nt < 4; nt++) {
            int m = wm * 64 + mt * 16 + (lane >> 2);
            int o = wn * 32 + nt * 8 + 2 * (lane & 3);
            const float* cf = c + (mt * 4 + nt) * 4;
            acc_s[o * 132 + m]           = cf[0];
            acc_s[(o + 1) * 132 + m]     = cf[1];
            acc_s[o * 132 + m + 8]       = cf[2];
            acc_s[(o + 1) * 132 + m + 8] = cf[3];
        }

    for (int i = tid; i < 4096; i += 256) {
        int o = i >> 5, n = i & 31;
        node_t[o * 33 + n] = g_out_node_t[b * 4096 + i];
    }
    if (tid < 128) {
        int bv = board[(b * 128 + h) * 128 + tid];
        nidx_s[tid] = (bv >= 0 && bv < 32) ? c2n[bv] : -1;
    }
    __syncthreads();

#pragma unroll
    for (int it = 0; it < 16; it++) {
        int o = wid + it * 8;
        float bo = conv_b[o];
        float4 a4 = *(const float4*)&acc_s[o * 132 + 4 * lane];
        int4  nd  = *(const int4*)&nidx_s[4 * lane];
        const float* nr = node_t + o * 33;
        float4 v;
        v.x = a4.x + bo + (nd.x >= 0 ? nr[nd.x] : 0.f);
        v.y = a4.y + bo + (nd.y >= 0 ? nr[nd.y] : 0.f);
        v.z = a4.z + bo + (nd.z >= 0 ? nr[nd.z] : 0.f);
        v.w = a4.w + bo + (nd.w >= 0 ? nr[nd.w] : 0.f);
        *(float4*)(out + (((size_t)(b * 128 + o) * 128) + h) * 128 + 4 * lane) = v;
    }
}

// ---------------------------------------------------------------------------
extern "C" void kernel_launch(void* const* d_in, const int* in_sizes, int n_in,
                              void* d_out, int out_size) {
    const int*   game_board   = (const int*)  d_in[0];
    const float* state        = (const float*)d_in[1];
    const float* node_embeds  = (const float*)d_in[2];
    const float* goal_embed   = (const float*)d_in[3];
    const int*   char_to_node = (const int*)  d_in[4];
    const float* conv_w       = (const float*)d_in[5];
    const float* conv_b       = (const float*)d_in[6];
    const float* wQ           = (const float*)d_in[7];
    const float* wK           = (const float*)d_in[8];
    const float* wV           = (const float*)d_in[9];
    const float* final_w      = (const float*)d_in[10];
    const float* final_b      = (const float*)d_in[11];
    float* out = (float*)d_out;

    cudaFuncSetAttribute(conv_mma_kernel,
                         cudaFuncAttributeMaxDynamicSharedMemorySize, CONV_SMEM);

    aux_kernel<<<AUX_TOTAL_BLKS, 256>>>(state, conv_w, node_embeds, goal_embed,
                                        wQ, wK, wV, final_w, final_b);
    conv_mma_kernel<<<dim3(128, 32), 256, CONV_SMEM>>>(conv_b, game_board,
                                                       char_to_node, out);
}

// round 14
// speedup vs baseline: 1.2767x; 1.2767x over previous
#include <cuda_runtime.h>
#include <cuda_fp16.h>
#include <math.h>
#include <cstdint>

#define B_    32
#define N_    32
#define E_    128
#define CIN_  64
#define COUT_ 128
#define H_    128
#define W_    128

// ---------------------------------------------------------------------------
// Device scratch
// ---------------------------------------------------------------------------
__device__ float g_out_node_t[B_ * COUT_ * N_];      // [b][o][n]
__device__ __half g_state_f16[B_ * H_ * W_ * CIN_];  // BHWC fp16
__device__ __half g_wt_f16[9 * COUT_ * CIN_];        // [kk][cout][cin] fp16
__device__ float g_Qn[N_ * E_];                      // node @ wQ_top
__device__ float g_Kn[N_ * E_];
__device__ float g_Vn[N_ * E_];

// ---------------------------------------------------------------------------
// Helpers
// ---------------------------------------------------------------------------
__device__ __forceinline__ uint32_t smem_u32(const void* p) {
    uint32_t a;
    asm("{ .reg .u64 t; cvta.to.shared.u64 t, %1; cvt.u32.u64 %0, t; }" : "=r"(a) : "l"(p));
    return a;
}
#define SWZ(o) ((o) ^ (((o) >> 3) & 0x70))

__device__ __forceinline__ void cp_async16(uint32_t dst, const void* src, uint32_t srcsize) {
    asm volatile("cp.async.cg.shared.global [%0], [%1], 16, %2;"
                 :: "r"(dst), "l"(src), "r"(srcsize) : "memory");
}
#define CP_COMMIT() asm volatile("cp.async.commit_group;" ::: "memory")

__device__ __forceinline__ void ldm_x4(uint32_t* r, uint32_t addr) {
    asm volatile("ldmatrix.sync.aligned.m8n8.x4.shared.b16 {%0,%1,%2,%3}, [%4];"
                 : "=r"(r[0]), "=r"(r[1]), "=r"(r[2]), "=r"(r[3]) : "r"(addr));
}
__device__ __forceinline__ void mma_fp16(float* c, const uint32_t* a,
                                         uint32_t b0, uint32_t b1) {
    asm volatile(
        "mma.sync.aligned.m16n8k16.row.col.f32.f16.f16.f32 "
        "{%0,%1,%2,%3}, {%4,%5,%6,%7}, {%8,%9}, {%0,%1,%2,%3};"
        : "+f"(c[0]), "+f"(c[1]), "+f"(c[2]), "+f"(c[3])
        : "r"(a[0]), "r"(a[1]), "r"(a[2]), "r"(a[3]), "r"(b0), "r"(b1));
}
__device__ __forceinline__ float dot4(float4 a, float4 b) {
    return a.x * b.x + a.y * b.y + a.z * b.z + a.w * b.w;
}

// ---------------------------------------------------------------------------
// Kernel 1 (mega-aux): QKV-pre ∪ w-convert ∪ state-convert (small work first).
//   blocks [0, 16)        : Qn/Kn/Vn = node_embeds @ w*_top
//   blocks [16, 304)      : conv weights -> [kk][cout][cin] fp16
//   blocks [304, 4400)    : state fp32 NCHW -> fp16 BHWC (float4 fat blocks)
// ---------------------------------------------------------------------------
#define AUX_QKV_BLKS   16
#define AUX_W_BLKS     288
#define AUX_STATE_BLKS 4096
#define AUX_TOTAL_BLKS (AUX_QKV_BLKS + AUX_W_BLKS + AUX_STATE_BLKS)

__global__ void __launch_bounds__(256)
aux_kernel(const float* __restrict__ state,
           const float* __restrict__ conv_w,
           const float* __restrict__ node_embeds,
           const float* __restrict__ wQ,
           const float* __restrict__ wK,
           const float* __restrict__ wV) {
    __shared__ __align__(16) float4 sf4[64 * 32];   // 32KB, state branch only
    const int bx  = blockIdx.x;
    const int tid = threadIdx.x;

    if (bx < AUX_QKV_BLKS) {
        // ---- Qn/Kn/Vn ----
        const int n = bx * 2 + (tid >> 7);
        const int k = tid & 127;
        float aq = 0.f, ak = 0.f, av = 0.f;
#pragma unroll 4
        for (int f = 0; f < 128; f++) {
            float nv = __ldg(&node_embeds[n * 128 + f]);
            aq += nv * __ldg(&wQ[f * 128 + k]);
            ak += nv * __ldg(&wK[f * 128 + k]);
            av += nv * __ldg(&wV[f * 128 + k]);
        }
        g_Qn[n * 128 + k] = aq;
        g_Kn[n * 128 + k] = ak;
        g_Vn[n * 128 + k] = av;
    } else if (bx < AUX_QKV_BLKS + AUX_W_BLKS) {
        // ---- weight transpose/convert ----
        int i = (bx - AUX_QKV_BLKS) * 256 + tid;
        int kk = i >> 13;
        int r  = i & 8191;
        int o  = r >> 6;
        int c  = r & 63;
        g_wt_f16[i] = __float2half_rn(conv_w[(o * 64 + c) * 9 + kk]);
    } else {
        // ---- state convert: sx = hh + 128*b, full 64c x 128w row per block
        const int sx = bx - AUX_QKV_BLKS - AUX_W_BLKS;
        const int hh = sx & 127;
        const int b  = sx >> 7;
        float* sf = (float*)sf4;

        // Phase A: LDG.128 (coalesced 512B/warp), swizzled STS.128
#pragma unroll
        for (int p = 0; p < 8; p++) {
            int i  = tid + p * 256;               // 0..2047
            int c  = i >> 5;
            int w4 = i & 31;
            float4 v = *(const float4*)(state +
                (((size_t)(b * 64 + c) * 128 + hh) * 128) + 4 * w4);
            sf4[c * 32 + (w4 ^ (c >> 3))] = v;
        }
        __syncthreads();

        // Phase B: conflict-free 8-channel gather per (w), uint4 STG
        const int ck = tid & 7;
#pragma unroll
        for (int q = 0; q < 4; q++) {
            int w = 32 * q + (tid >> 3);
            union { __half h[8]; uint4 u; } ph;
#pragma unroll
            for (int j = 0; j < 8; j++) {
                int c = ck * 8 + j;               // c>>3 == ck
                float x = sf[c * 128 + (((w >> 2) ^ ck) << 2) + (w & 3)];
                ph.h[j] = __float2half_rn(x);
            }
            *(uint4*)(g_state_f16 +
                (((size_t)(b * 128 + hh) * 128) + w) * 64 + ck * 8) = ph.u;
        }
    }
}

// ---------------------------------------------------------------------------
// Kernel 2: per-batch attention; S0 and Vnf recomputed per block. grid 32x256.
// ---------------------------------------------------------------------------
__global__ void __launch_bounds__(256)
attn_perb(const float* __restrict__ goal_embed,
          const float* __restrict__ wQ,
          const float* __restrict__ wK,
          const float* __restrict__ wV,
          const float* __restrict__ final_w,
          const float* __restrict__ final_b) {
    __shared__ float sg[128], sqg[128], skg[128], svg[128];
    __shared__ float su[32], sv[32], ss0[1], svgf[128];
    __shared__ float sP[32 * 32];
    __shared__ float vnf_s[128 * 33];       // [o][n] pad 33
    const int b = blockIdx.x;
    const int tid = threadIdx.x;

    if (tid < 128) sg[tid] = goal_embed[b * 128 + tid];
    __syncthreads();

    // qg / kg (256 threads), then vg (128 threads)
    {
        int k = tid & 127;
        const float* w = (tid >> 7) ? wK : wQ;
        float acc = 0.f;
#pragma unroll 4
        for (int f = 0; f < 128; f++) acc += sg[f] * __ldg(&w[(128 + f) * 128 + k]);
        ((tid >> 7) ? skg : sqg)[k] = acc;
    }
    if (tid < 128) {
        float acc = 0.f;
#pragma unroll 4
        for (int f = 0; f < 128; f++) acc += sg[f] * __ldg(&wV[(128 + f) * 128 + tid]);
        svg[tid] = acc;
    }
    __syncthreads();

    // rank-1 pieces + Vnf (parallel)
    if (tid < 32) {
        const float4* qa = (const float4*)(g_Qn + tid * 128);
        float a = 0.f;
#pragma unroll
        for (int t = 0; t < 32; t++) a += dot4(__ldg(&qa[t]), *(float4*)&skg[t * 4]);
        su[tid] = a;
    } else if (tid < 64) {
        const float4* ka = (const float4*)(g_Kn + (tid - 32) * 128);
        float a = 0.f;
#pragma unroll
        for (int t = 0; t < 32; t++) a += dot4(__ldg(&ka[t]), *(float4*)&sqg[t * 4]);
        sv[tid - 32] = a;
    } else if (tid == 64) {
        float a = 0.f;
#pragma unroll
        for (int t = 0; t < 32; t++) a += dot4(*(float4*)&sqg[t * 4], *(float4*)&skg[t * 4]);
        ss0[0] = a;
    } else if (tid >= 128) {
        int o = tid - 128;
        const float4* fw = (const float4*)(final_w + o * 128);
        float a = __ldg(&final_b[o]);
#pragma unroll
        for (int t = 0; t < 32; t++) a += dot4(*(float4*)&svg[t * 4], __ldg(&fw[t]));
        svgf[o] = a;
    }
    // Vnf[n][o] = Vn[n] . final_w[o]
    for (int i = tid; i < 4096; i += 256) {
        int n = i >> 7, o = i & 127;
        const float4* va = (const float4*)(g_Vn + n * 128);
        const float4* fw = (const float4*)(final_w + o * 128);
        float a = 0.f;
#pragma unroll
        for (int t = 0; t < 32; t++) a += dot4(__ldg(&va[t]), __ldg(&fw[t]));
        vnf_s[o * 33 + n] = a;
    }
    __syncthreads();

    // scores (S0 recomputed locally + rank-1 corrections)
    {
        int q = tid >> 3, n0 = (tid & 7) * 4;
        const float4* qa = (const float4*)(g_Qn + q * 128);
#pragma unroll
        for (int j = 0; j < 4; j++) {
            int n = n0 + j;
            const float4* ka = (const float4*)(g_Kn + n * 128);
            float a = 0.f;
#pragma unroll
            for (int t = 0; t < 32; t++) a += dot4(__ldg(&qa[t]), __ldg(&ka[t]));
            sP[q * 32 + n] = (a + su[q] + sv[n] + ss0[0]) * 0.08838834764831845f;
        }
    }
    __syncthreads();

    // softmax rows
    if (tid < 32) {
        const int q = tid;
        float mx = -1e30f;
#pragma unroll
        for (int n = 0; n < 32; n++) mx = fmaxf(mx, sP[q * 32 + n]);
        float s = 0.f;
#pragma unroll
        for (int n = 0; n < 32; n++) {
            float e = expf(sP[q * 32 + n] - mx);
            sP[q * 32 + n] = e;
            s += e;
        }
        float inv = 1.f / s;
#pragma unroll
        for (int n = 0; n < 32; n++) sP[q * 32 + n] *= inv;
    }
    __syncthreads();

    // out_node_t[b][o][q] = P[q] . vnf[:, o] + svgf[o]
    {
        int o = tid >> 1, q0 = (tid & 1) * 16;
        const float* vr = vnf_s + o * 33;
#pragma unroll
        for (int qq = 0; qq < 16; qq++) {
            int q = q0 + qq;
            float a = svgf[o];
#pragma unroll
            for (int n = 0; n < 32; n++) a += sP[q * 32 + n] * vr[n];
            g_out_node_t[b * 4096 + o * 32 + q] = a;
        }
    }
}

// ---------------------------------------------------------------------------
// Kernel 3: conv as fp16 mma.sync GEMM, 2 CTAs/SM, 3-stage B ring.
// CTA = (h, b): M=128 pixels, N=128 couts, K = 9 x 64.
// SMEM: A 48KB + B 3x16KB + zero. 256 threads, warp tile 64x32.
// ---------------------------------------------------------------------------
#define SMEM_B_OFF   49152
#define SMEM_Z_OFF   98304
#define CONV_SMEM    98560
#define NODET_OFF    67584
#define NIDX_OFF     84480

__global__ void __launch_bounds__(256, 2)
conv_mma_kernel(const float* __restrict__ conv_b,
                const int*   __restrict__ board,
                const int*   __restrict__ c2n,
                float*       __restrict__ out) {
    extern __shared__ char smem[];
    const uint32_t sA = smem_u32(smem);
    const int h   = blockIdx.x;
    const int b   = blockIdx.y;
    const int tid = threadIdx.x;
    const int lane = tid & 31;
    const int wid  = tid >> 5;
    const int wm = wid & 1;
    const int wn = wid >> 1;

    if (tid < 16) *(uint4*)(smem + SMEM_Z_OFF + tid * 16) = make_uint4(0, 0, 0, 0);

    // ---- stage A: 3 input rows (h-1..h+1) ----
#pragma unroll
    for (int t = 0; t < 12; t++) {
        int i = tid + t * 256;
        int r = i >> 10;
        int j = i & 1023;
        int w = j >> 3, ck = j & 7;
        int hr = h - 1 + r;
        uint32_t oksz = ((unsigned)hr < 128u) ? 16u : 0u;
        int hrc = hr < 0 ? 0 : (hr > 127 ? 127 : hr);
        const void* src = g_state_f16 + (((size_t)(b * 128 + hrc) * 128) + w) * 64 + ck * 8;
        cp_async16(sA + r * 16384 + SWZ(w * 128 + ck * 16), src, oksz);
    }
    // ---- B tap 0 -> buf0 (group 0, with A) ----
#pragma unroll
    for (int t = 0; t < 4; t++) {
        int i = tid + t * 256;
        int n = i >> 3, ck = i & 7;
        cp_async16(sA + SMEM_B_OFF + SWZ(n * 128 + ck * 16),
                   g_wt_f16 + n * 64 + ck * 8, 16);
    }
    CP_COMMIT();
    // ---- B tap 1 -> buf1 (group 1) ----
#pragma unroll
    for (int t = 0; t < 4; t++) {
        int i = tid + t * 256;
        int n = i >> 3, ck = i & 7;
        cp_async16(sA + SMEM_B_OFF + 16384 + SWZ(n * 128 + ck * 16),
                   g_wt_f16 + 8192 + n * 64 + ck * 8, 16);
    }
    CP_COMMIT();

    float c[64];
#pragma unroll
    for (int j = 0; j < 64; j++) c[j] = 0.f;

    const int lrow = lane & 15;
    const uint32_t khA = (uint32_t)((lane >> 4) << 4);
    const int nrow = (lane & 7) | ((lane & 16) >> 1);
    const uint32_t khB = (uint32_t)(((lane >> 3) & 1) << 4);
    const int wb0 = wm * 64 + lrow;
    const uint32_t zaddr = sA + SMEM_Z_OFF;
    int nbs[2];
#pragma unroll
    for (int nt2 = 0; nt2 < 2; nt2++) nbs[nt2] = wn * 32 + nt2 * 16 + nrow;

#pragma unroll
    for (int kk = 0; kk < 9; kk++) {
        if (kk < 8) asm volatile("cp.async.wait_group 1;" ::: "memory");
        else        asm volatile("cp.async.wait_group 0;" ::: "memory");
        __syncthreads();

        // prefetch tap kk+2 into buf (kk+2)%3
        if (kk <= 6) {
            const __half* src_base = g_wt_f16 + (kk + 2) * 8192;
            const uint32_t dst_base = sA + SMEM_B_OFF + (uint32_t)((kk + 2) % 3) * 16384;
#pragma unroll
            for (int t = 0; t < 4; t++) {
                int i = tid + t * 256;
                int n = i >> 3, ck = i & 7;
                cp_async16(dst_base + SWZ(n * 128 + ck * 16), src_base + n * 64 + ck * 8, 16);
            }
            CP_COMMIT();
        }

        const int dy = kk / 3, dx = kk - dy * 3;
        uint32_t aHi[4], aXr[4];
#pragma unroll
        for (int mt = 0; mt < 4; mt++) {
            int wv = wb0 + mt * 16 + dx - 1;
            bool ok = (unsigned)wv < 128u;
            aHi[mt] = ok ? (sA + (uint32_t)dy * 16384 + (uint32_t)wv * 128) : zaddr;
            aXr[mt] = ok ? (uint32_t)((wv & 7) << 4) : 0u;
        }
        const uint32_t bB = sA + SMEM_B_OFF + (uint32_t)(kk % 3) * 16384;
        uint32_t bHi[2], bXr[2];
#pragma unroll
        for (int nt2 = 0; nt2 < 2; nt2++) {
            bHi[nt2] = bB + (uint32_t)nbs[nt2] * 128;
            bXr[nt2] = (uint32_t)((nbs[nt2] & 7) << 4);
        }

#pragma unroll
        for (int ks = 0; ks < 4; ks++) {
            const uint32_t kA = (uint32_t)(ks * 32) + khA;
            const uint32_t kB = (uint32_t)(ks * 32) + khB;
            uint32_t bh[8];
            ldm_x4(bh,     bHi[0] + (kB ^ bXr[0]));
            ldm_x4(bh + 4, bHi[1] + (kB ^ bXr[1]));
            uint32_t ah[16];
#pragma unroll
            for (int mt = 0; mt < 4; mt++)
                ldm_x4(ah + 4 * mt, aHi[mt] + (kA ^ aXr[mt]));
#pragma unroll
            for (int mt = 0; mt < 4; mt++)
#pragma unroll
                for (int nt = 0; nt < 4; nt++) {
                    int bi = (nt >> 1) * 4 + (nt & 1) * 2;
                    mma_fp16(c + (mt * 4 + nt) * 4, ah + 4 * mt, bh[bi], bh[bi + 1]);
                }
        }
    }
    __syncthreads();

    // ---- epilogue ----
    float* acc_s  = (float*)smem;                 // 128 x 132
    float* node_t = (float*)(smem + NODET_OFF);   // [o][n] pad 33
    int*   nidx_s = (int*)(smem + NIDX_OFF);

#pragma unroll
    for (int mt = 0; mt < 4; mt++)
#pragma unroll
        for (int nt = 0; nt < 4; nt++) {
            int m = wm * 64 + mt * 16 + (lane >> 2);
            int o = wn * 32 + nt * 8 + 2 * (lane & 3);
            const float* cf = c + (mt * 4 + nt) * 4;
            acc_s[o * 132 + m]           = cf[0];
            acc_s[(o + 1) * 132 + m]     = cf[1];
            acc_s[o * 132 + m + 8]       = cf[2];
            acc_s[(o + 1) * 132 + m + 8] = cf[3];
        }

    for (int i = tid; i < 4096; i += 256) {
        int o = i >> 5, n = i & 31;
        node_t[o * 33 + n] = g_out_node_t[b * 4096 + i];
    }
    if (tid < 128) {
        int bv = board[(b * 128 + h) * 128 + tid];
        nidx_s[tid] = (bv >= 0 && bv < 32) ? c2n[bv] : -1;
    }
    __syncthreads();

#pragma unroll
    for (int it = 0; it < 16; it++) {
        int o = wid + it * 8;
        float bo = conv_b[o];
        float4 a4 = *(const float4*)&acc_s[o * 132 + 4 * lane];
        int4  nd  = *(const int4*)&nidx_s[4 * lane];
        const float* nr = node_t + o * 33;
        float4 v;
        v.x = a4.x + bo + (nd.x >= 0 ? nr[nd.x] : 0.f);
        v.y = a4.y + bo + (nd.y >= 0 ? nr[nd.y] : 0.f);
        v.z = a4.z + bo + (nd.z >= 0 ? nr[nd.z] : 0.f);
        v.w = a4.w + bo + (nd.w >= 0 ? nr[nd.w] : 0.f);
        *(float4*)(out + (((size_t)(b * 128 + o) * 128) + h) * 128 + 4 * lane) = v;
    }
}

// ---------------------------------------------------------------------------
extern "C" void kernel_launch(void* const* d_in, const int* in_sizes, int n_in,
                              void* d_out, int out_size) {
    const int*   game_board   = (const int*)  d_in[0];
    const float* state        = (const float*)d_in[1];
    const float* node_embeds  = (const float*)d_in[2];
    const float* goal_embed   = (const float*)d_in[3];
    const int*   char_to_node = (const int*)  d_in[4];
    const float* conv_w       = (const float*)d_in[5];
    const float* conv_b       = (const float*)d_in[6];
    const float* wQ           = (const float*)d_in[7];
    const float* wK           = (const float*)d_in[8];
    const float* wV           = (const float*)d_in[9];
    const float* final_w      = (const float*)d_in[10];
    const float* final_b      = (const float*)d_in[11];
    float* out = (float*)d_out;

    cudaFuncSetAttribute(conv_mma_kernel,
                         cudaFuncAttributeMaxDynamicSharedMemorySize, CONV_SMEM);

    aux_kernel<<<AUX_TOTAL_BLKS, 256>>>(state, conv_w, node_embeds, wQ, wK, wV);
    attn_perb<<<32, 256>>>(goal_embed, wQ, wK, wV, final_w, final_b);
    conv_mma_kernel<<<dim3(128, 32), 256, CONV_SMEM>>>(conv_b, game_board,
                                                       char_to_node, out);
}